// round 9
// baseline (speedup 1.0000x reference)
#include <cuda_runtime.h>
#include <cuda_fp16.h>
#include <cstdint>

#define BB 64
#define NN 512
#define CC 1024
#define KC 64
#define NCH (CC/KC)          // 16 k-chunks
#define NSTG 3               // ring depth

// Scratch (allocation-free rule: __device__ globals)
__device__ float g_S[(size_t)BB * NN * NN];      // 67 MB gram matrices
__device__ float g_thr[BB * NN];
__device__ float g_rdeg[BB * NN];

// smem: 4 planes per buffer (A1,A2,B1,B2), 128 rows x 64 halves,
// padded row stride 144 B for conflict-free ldmatrix.
#define ROWB   144
#define TILE_B (128 * ROWB)          // 18432
#define BUF_B  (4 * TILE_B)          // 73728
#define SMEM_TOTAL (NSTG * BUF_B)    // 221184

#define NTHR 640                     // 16 MMA warps (4/SMSP) + 4 producer warps

// named barriers: FULL[s] = 1+s, EMPTY[s] = 4+s
#define BAR_SYNC(id)   asm volatile("bar.sync %0, %1;"   :: "r"(id), "n"(NTHR) : "memory")
#define BAR_ARRIVE(id) asm volatile("bar.arrive %0, %1;" :: "r"(id), "n"(NTHR) : "memory")

__device__ __forceinline__ uint32_t smem_u32(const void* p) {
    uint32_t a;
    asm("{ .reg .u64 t; cvta.to.shared.u64 t, %1; cvt.u32.u64 %0, t; }"
        : "=r"(a) : "l"(p));
    return a;
}
__device__ __forceinline__ void ldsm4(uint32_t& r0, uint32_t& r1,
                                      uint32_t& r2, uint32_t& r3, uint32_t a) {
    asm volatile("ldmatrix.sync.aligned.m8n8.x4.shared.b16 {%0,%1,%2,%3}, [%4];"
                 : "=r"(r0), "=r"(r1), "=r"(r2), "=r"(r3) : "r"(a));
}
__device__ __forceinline__ void mma16816(float* d, const uint32_t* a,
                                         uint32_t b0, uint32_t b1) {
    asm volatile(
        "mma.sync.aligned.m16n8k16.row.col.f32.f16.f16.f32 "
        "{%0,%1,%2,%3}, {%4,%5,%6,%7}, {%8,%9}, {%0,%1,%2,%3};"
        : "+f"(d[0]), "+f"(d[1]), "+f"(d[2]), "+f"(d[3])
        : "r"(a[0]), "r"(a[1]), "r"(a[2]), "r"(a[3]), "r"(b0), "r"(b1));
}

// ---------------------------------------------------------------------------
// Kernel A: warp-specialized HMMA split-fp16 GEMM, 3-stage ring, KC=64.
// S = H1 H1^T + H1 H2^T + H2 H1^T, fp32 accumulation (exact to ~2^-22).
// 16 MMA consumer warps (4 per SMSP; 32x32 sub-tile each) so HMMA completion
// latency is covered by warp-level parallelism; 4 producer warps convert
// fp32 -> 2xfp16 in flight.
// ---------------------------------------------------------------------------
__global__ __launch_bounds__(NTHR, 1)
void gemm_ws_kernel(const float* __restrict__ X)
{
    extern __shared__ __align__(16) char smem[];
    const unsigned char ITm[10] = {0,0,0,0,1,1,1,2,2,3};
    const unsigned char JTm[10] = {0,1,2,3,1,2,3,2,3,3};
    const int it = ITm[blockIdx.x];
    const int jt = JTm[blockIdx.x];
    const int b  = blockIdx.y;
    const int rbase = it * 128;
    const int cbase = jt * 128;

    const int tid  = threadIdx.x;
    const int wid  = tid >> 5;
    const int lane = tid & 31;
    const uint32_t sb = smem_u32(smem);
    const float* __restrict__ Xb = X + (size_t)b * NN * CC;

    float acc[2][4][4];
    #pragma unroll
    for (int f = 0; f < 2; f++)
        #pragma unroll
        for (int n = 0; n < 4; n++)
            #pragma unroll
            for (int q = 0; q < 4; q++) acc[f][n][q] = 0.0f;

    if (wid >= 16) {
        // ---------------- producer warps (128 threads) ----------------
        const int ptid = tid - 512;          // 0..127
        uint32_t bufoff = 0;
        #pragma unroll 1
        for (int c = 0; c < NCH; c++) {
            const int s = c - (c / NSTG) * NSTG;      // c % 3
            if (c >= NSTG) BAR_SYNC(4 + s);           // wait EMPTY[s]
            char* base = smem + bufoff;
            const int k0 = c * KC;
            #pragma unroll
            for (int i = 0; i < 32; i++) {
                int u  = i * 128 + ptid;     // 0..4095 16B-units
                int t  = u >> 11;            // 0=A rows, 1=B rows
                int r  = (u >> 4) & 127;
                int f4 = u & 15;
                int grow = (t ? cbase : rbase) + r;
                float4 v = *(const float4*)(Xb + (size_t)grow * CC + k0 + f4 * 4);
                __half2 a1 = __floats2half2_rn(v.x, v.y);
                __half2 b1 = __floats2half2_rn(v.z, v.w);
                float2 fa = __half22float2(a1);
                float2 fb = __half22float2(b1);
                __half2 a2 = __floats2half2_rn(v.x - fa.x, v.y - fa.y);
                __half2 b2 = __floats2half2_rn(v.z - fb.x, v.w - fb.y);
                int off = r * ROWB + f4 * 8;
                *(uint2*)(base + (t*2+0) * TILE_B + off) =
                    make_uint2(*(uint32_t*)&a1, *(uint32_t*)&b1);
                *(uint2*)(base + (t*2+1) * TILE_B + off) =
                    make_uint2(*(uint32_t*)&a2, *(uint32_t*)&b2);
            }
            BAR_ARRIVE(1 + s);               // signal FULL[s]
            bufoff += BUF_B;
            if (bufoff == NSTG * BUF_B) bufoff = 0;
        }
    } else {
        // ---------------- MMA consumer warps (16) ----------------
        const int wm = wid >> 2;             // 0..3 -> 32-row slab
        const int wn = wid & 3;              // 0..3 -> 32-col slab
        const int lrow = lane & 15;
        const int lcol = (lane >> 4) * 16;

        const uint32_t aoff = (uint32_t)((wm * 32 + lrow) * ROWB + lcol);
        const uint32_t boff = (uint32_t)((wn * 32 + lrow) * ROWB + lcol);
        uint32_t bufoff = 0;

        #pragma unroll 1
        for (int c = 0; c < NCH; c++) {
            const int s = c - (c / NSTG) * NSTG;
            BAR_SYNC(1 + s);                 // wait FULL[s]

            const uint32_t tb  = sb + bufoff;
            const uint32_t aB1 = tb + aoff;
            const uint32_t aB2 = tb + TILE_B + aoff;
            const uint32_t bB1 = tb + 2 * TILE_B + boff;
            const uint32_t bB2 = tb + 3 * TILE_B + boff;

            #pragma unroll
            for (int ks = 0; ks < 4; ks++) {
                const int kb = ks * 32;      // compile-time under unroll
                uint32_t a1f[2][4], a2f[2][4], b1f[2][4], b2f[2][4];
                #pragma unroll
                for (int f = 0; f < 2; f++) {
                    ldsm4(a1f[f][0], a1f[f][1], a1f[f][2], a1f[f][3],
                          aB1 + (f * 16 * ROWB + kb));
                    ldsm4(a2f[f][0], a2f[f][1], a2f[f][2], a2f[f][3],
                          aB2 + (f * 16 * ROWB + kb));
                }
                #pragma unroll
                for (int g = 0; g < 2; g++) {
                    ldsm4(b1f[g][0], b1f[g][1], b1f[g][2], b1f[g][3],
                          bB1 + (g * 16 * ROWB + kb));
                    ldsm4(b2f[g][0], b2f[g][1], b2f[g][2], b2f[g][3],
                          bB2 + (g * 16 * ROWB + kb));
                }
                // stream 1: H1 x H1 (8 independent MMAs)
                #pragma unroll
                for (int f = 0; f < 2; f++)
                    #pragma unroll
                    for (int g = 0; g < 2; g++)
                        #pragma unroll
                        for (int h = 0; h < 2; h++)
                            mma16816(acc[f][g*2+h], a1f[f],
                                     b1f[g][0+h], b1f[g][2+h]);
                // stream 2: H1 x H2
                #pragma unroll
                for (int f = 0; f < 2; f++)
                    #pragma unroll
                    for (int g = 0; g < 2; g++)
                        #pragma unroll
                        for (int h = 0; h < 2; h++)
                            mma16816(acc[f][g*2+h], a1f[f],
                                     b2f[g][0+h], b2f[g][2+h]);
                // stream 3: H2 x H1
                #pragma unroll
                for (int f = 0; f < 2; f++)
                    #pragma unroll
                    for (int g = 0; g < 2; g++)
                        #pragma unroll
                        for (int h = 0; h < 2; h++)
                            mma16816(acc[f][g*2+h], a2f[f],
                                     b1f[g][0+h], b1f[g][2+h]);
            }
            BAR_ARRIVE(4 + s);               // signal EMPTY[s]
            bufoff += BUF_B;
            if (bufoff == NSTG * BUF_B) bufoff = 0;
        }
    }

    __syncthreads();

    // ---- epilogue (consumer warps hold acc) ----
    float* __restrict__ Sb = g_S + (size_t)b * NN * NN;
    const int r0 = lane >> 2;
    const int c0 = (lane & 3) * 2;
    const int wm = wid >> 2;
    const int wn = wid & 3;

    if (wid < 16) {
        #pragma unroll
        for (int f = 0; f < 2; f++) {
            const int gr = rbase + wm * 32 + f * 16 + r0;
            #pragma unroll
            for (int n = 0; n < 4; n++) {
                const int gc = cbase + wn * 32 + n * 8 + c0;
                float* d = acc[f][n];
                *(float2*)&Sb[(size_t)gr * NN + gc]       = make_float2(d[0], d[1]);
                *(float2*)&Sb[(size_t)(gr + 8) * NN + gc] = make_float2(d[2], d[3]);
            }
        }
    }

    // mirror via smem transpose (coalesced both sides)
    if (jt > it) {
        float* st = (float*)smem;            // 128 x 129 floats = 66048 B
        if (wid < 16) {
            #pragma unroll
            for (int f = 0; f < 2; f++) {
                const int sr = wm * 32 + f * 16 + r0;
                #pragma unroll
                for (int n = 0; n < 4; n++) {
                    const int sc = wn * 32 + n * 8 + c0;
                    float* d = acc[f][n];
                    st[(size_t)sr * 129 + sc]           = d[0];
                    st[(size_t)sr * 129 + sc + 1]       = d[1];
                    st[(size_t)(sr + 8) * 129 + sc]     = d[2];
                    st[(size_t)(sr + 8) * 129 + sc + 1] = d[3];
                }
            }
        }
        __syncthreads();
        if (tid < 256) {
            const int mr = tid >> 1;         // mirror row = tile column
            const int hh = tid & 1;          // 64-wide half
            float* dst = Sb + (size_t)(cbase + mr) * NN + rbase + hh * 64;
            #pragma unroll
            for (int i = 0; i < 16; i++) {
                float4 v;
                v.x = st[(size_t)(hh * 64 + i * 4 + 0) * 129 + mr];
                v.y = st[(size_t)(hh * 64 + i * 4 + 1) * 129 + mr];
                v.z = st[(size_t)(hh * 64 + i * 4 + 2) * 129 + mr];
                v.w = st[(size_t)(hh * 64 + i * 4 + 3) * 129 + mr];
                *(float4*)(dst + i * 4) = v;
            }
        }
    }
}

// ---------------------------------------------------------------------------
// Kernel B: one WARP per row; exact 32nd-largest via bitwise radix select.
// ---------------------------------------------------------------------------
__global__ __launch_bounds__(256)
void topk_threshold_kernel()
{
    const int row  = blockIdx.x * 8 + (threadIdx.x >> 5);
    const int lane = threadIdx.x & 31;
    const float* __restrict__ Sr = g_S + (size_t)row * NN;

    uint32_t u[16];
    const float4* S4 = (const float4*)Sr;
    #pragma unroll
    for (int j = 0; j < 4; j++) {
        float4 t = S4[lane + 32 * j];
        float f[4] = {t.x, t.y, t.z, t.w};
        #pragma unroll
        for (int q = 0; q < 4; q++) {
            uint32_t s = __float_as_uint(f[q]);
            u[4*j+q] = (s & 0x80000000u) ? ~s : (s | 0x80000000u);
        }
    }

    uint32_t thr = 0;
    #pragma unroll 1
    for (int bit = 31; bit >= 0; bit--) {
        const uint32_t test = thr | (1u << bit);
        int c = 0;
        #pragma unroll
        for (int j = 0; j < 16; j++) c += (u[j] >= test);
        c = __reduce_add_sync(0xffffffffu, c);
        if (c >= 32) thr = test;
    }

    int cnt = 0;
    #pragma unroll
    for (int j = 0; j < 16; j++) cnt += (u[j] >= thr);
    cnt = __reduce_add_sync(0xffffffffu, cnt);

    if (lane == 0) {
        float tf = (thr & 0x80000000u) ? __uint_as_float(thr & 0x7fffffffu)
                                       : __uint_as_float(~thr);
        g_thr[row]  = tf;
        g_rdeg[row] = rsqrtf((float)cnt);
    }
}

// ---------------------------------------------------------------------------
// Kernel C: out[b,i,j] = (S >= thr_i) ? rdeg_i * rdeg_j : 0
// ---------------------------------------------------------------------------
__global__ __launch_bounds__(256)
void normalize_kernel(float* __restrict__ out)
{
    const size_t idx = (size_t)blockIdx.x * blockDim.x + threadIdx.x;
    const int j4  = (int)(idx % (NN / 4));
    const int row = (int)(idx / (NN / 4));
    const int b   = row / NN;

    const float thr = g_thr[row];
    const float ri  = g_rdeg[row];
    const float4 s  = *(const float4*)(g_S + (size_t)row * NN + j4 * 4);
    const float* rj = g_rdeg + b * NN + j4 * 4;

    float4 o;
    o.x = (s.x >= thr) ? ri * rj[0] : 0.0f;
    o.y = (s.y >= thr) ? ri * rj[1] : 0.0f;
    o.z = (s.z >= thr) ? ri * rj[2] : 0.0f;
    o.w = (s.w >= thr) ? ri * rj[3] : 0.0f;
    ((float4*)out)[idx] = o;
}

// ---------------------------------------------------------------------------
extern "C" void kernel_launch(void* const* d_in, const int* in_sizes, int n_in,
                              void* d_out, int out_size)
{
    const float* x = (const float*)d_in[0];
    float* out = (float*)d_out;

    cudaFuncSetAttribute(gemm_ws_kernel,
                         cudaFuncAttributeMaxDynamicSharedMemorySize, SMEM_TOTAL);

    dim3 gGemm(10, BB);
    gemm_ws_kernel<<<gGemm, NTHR, SMEM_TOTAL>>>(x);

    topk_threshold_kernel<<<BB * NN / 8, 256>>>();

    const int n4 = BB * NN * NN / 4;
    normalize_kernel<<<n4 / 256, 256>>>(out);
}

// round 10
// speedup vs baseline: 1.2764x; 1.2764x over previous
#include <cuda_runtime.h>
#include <cuda_fp16.h>
#include <cstdint>

#define BB 64
#define NN 512
#define CC 1024
#define KC 64
#define NCH (CC/KC)          // 16 k-chunks

// Scratch (allocation-free rule: __device__ globals)
__device__ float g_S[(size_t)BB * NN * NN];      // 67 MB gram matrices
__device__ uint32_t g_mask[BB * NN * 16];        // 2 MB adjacency ballots
__device__ float g_rdeg[BB * NN];

// smem: 4 planes per buffer (A1,A2,B1,B2), 128 rows x 64 halves,
// padded row stride 144 B for conflict-free ldmatrix.
#define ROWB   144
#define TILE_B (128 * ROWB)          // 18432
#define BUF_B  (4 * TILE_B)          // 73728
#define SMEM_TOTAL (2 * BUF_B)       // 147456

#define NTHR 384                     // 8 MMA warps + 4 producer warps

// named barriers: FULL0=1, FULL1=2, EMPTY0=3, EMPTY1=4
#define BAR_SYNC(id)   asm volatile("bar.sync %0, %1;"   :: "r"(id), "n"(NTHR) : "memory")
#define BAR_ARRIVE(id) asm volatile("bar.arrive %0, %1;" :: "r"(id), "n"(NTHR) : "memory")

__device__ __forceinline__ uint32_t smem_u32(const void* p) {
    uint32_t a;
    asm("{ .reg .u64 t; cvta.to.shared.u64 t, %1; cvt.u32.u64 %0, t; }"
        : "=r"(a) : "l"(p));
    return a;
}
__device__ __forceinline__ void ldsm4(uint32_t& r0, uint32_t& r1,
                                      uint32_t& r2, uint32_t& r3, uint32_t a) {
    asm volatile("ldmatrix.sync.aligned.m8n8.x4.shared.b16 {%0,%1,%2,%3}, [%4];"
                 : "=r"(r0), "=r"(r1), "=r"(r2), "=r"(r3) : "r"(a));
}
__device__ __forceinline__ void mma16816(float* d, const uint32_t* a,
                                         uint32_t b0, uint32_t b1) {
    asm volatile(
        "mma.sync.aligned.m16n8k16.row.col.f32.f16.f16.f32 "
        "{%0,%1,%2,%3}, {%4,%5,%6,%7}, {%8,%9}, {%0,%1,%2,%3};"
        : "+f"(d[0]), "+f"(d[1]), "+f"(d[2]), "+f"(d[3])
        : "r"(a[0]), "r"(a[1]), "r"(a[2]), "r"(a[3]), "r"(b0), "r"(b1));
}

// ---------------------------------------------------------------------------
// Kernel A: warp-specialized HMMA split-fp16 GEMM (R6 configuration, the
// measured-best: 223.3 us, tensor ~48% = legacy-HMMA ceiling).
// S = H1 H1^T + H1 H2^T + H2 H1^T, fp32 accumulation (exact to ~2^-22).
// ---------------------------------------------------------------------------
__global__ __launch_bounds__(NTHR, 1)
void gemm_ws_kernel(const float* __restrict__ X)
{
    extern __shared__ __align__(16) char smem[];
    const unsigned char ITm[10] = {0,0,0,0,1,1,1,2,2,3};
    const unsigned char JTm[10] = {0,1,2,3,1,2,3,2,3,3};
    const int it = ITm[blockIdx.x];
    const int jt = JTm[blockIdx.x];
    const int b  = blockIdx.y;
    const int rbase = it * 128;
    const int cbase = jt * 128;

    const int tid  = threadIdx.x;
    const int wid  = tid >> 5;
    const int lane = tid & 31;
    const uint32_t sb = smem_u32(smem);
    const float* __restrict__ Xb = X + (size_t)b * NN * CC;

    float acc[4][4][4];
    #pragma unroll
    for (int f = 0; f < 4; f++)
        #pragma unroll
        for (int n = 0; n < 4; n++)
            #pragma unroll
            for (int q = 0; q < 4; q++) acc[f][n][q] = 0.0f;

    if (wid >= 8) {
        // ---------------- producer warps ----------------
        const int ptid = tid - 256;          // 0..127
        #pragma unroll 1
        for (int c = 0; c < NCH; c++) {
            const int bs = c & 1;
            if (c >= 2) BAR_SYNC(3 + bs);    // wait EMPTY[bs]
            char* base = smem + bs * BUF_B;
            const int k0 = c * KC;
            #pragma unroll
            for (int i = 0; i < 32; i++) {
                int u  = i * 128 + ptid;     // 0..4095 16B-units
                int t  = u >> 11;            // 0=A rows, 1=B rows
                int r  = (u >> 4) & 127;
                int f4 = u & 15;
                int grow = (t ? cbase : rbase) + r;
                float4 v = *(const float4*)(Xb + (size_t)grow * CC + k0 + f4 * 4);
                __half2 a1 = __floats2half2_rn(v.x, v.y);
                __half2 b1 = __floats2half2_rn(v.z, v.w);
                float2 fa = __half22float2(a1);
                float2 fb = __half22float2(b1);
                __half2 a2 = __floats2half2_rn(v.x - fa.x, v.y - fa.y);
                __half2 b2 = __floats2half2_rn(v.z - fb.x, v.w - fb.y);
                int off = r * ROWB + f4 * 8;
                *(uint2*)(base + (t*2+0) * TILE_B + off) =
                    make_uint2(*(uint32_t*)&a1, *(uint32_t*)&b1);
                *(uint2*)(base + (t*2+1) * TILE_B + off) =
                    make_uint2(*(uint32_t*)&a2, *(uint32_t*)&b2);
            }
            BAR_ARRIVE(1 + bs);              // signal FULL[bs]
        }
    } else {
        // ---------------- MMA consumer warps ----------------
        const int wm = wid >> 2;             // 0..1  -> 64-row slab
        const int wn = wid & 3;              // 0..3  -> 32-col slab
        const int lrow = lane & 15;
        const int lcol = (lane >> 4) * 16;

        #pragma unroll 1
        for (int c = 0; c < NCH; c++) {
            const int bs = c & 1;
            BAR_SYNC(1 + bs);                // wait FULL[bs]

            const uint32_t tb  = sb + bs * BUF_B;
            const uint32_t pA1 = tb;
            const uint32_t pA2 = tb + TILE_B;
            const uint32_t pB1 = tb + 2 * TILE_B;
            const uint32_t pB2 = tb + 3 * TILE_B;

            #pragma unroll
            for (int ks = 0; ks < 4; ks++) {
                const int kb = ks * 32;      // 16 halves = 32 B
                uint32_t a1[4][4], a2[4][4], b1r[2][4], b2r[2][4];
                #pragma unroll
                for (int f = 0; f < 4; f++) {
                    uint32_t ad = (wm * 64 + f * 16 + lrow) * ROWB + lcol + kb;
                    ldsm4(a1[f][0], a1[f][1], a1[f][2], a1[f][3], pA1 + ad);
                    ldsm4(a2[f][0], a2[f][1], a2[f][2], a2[f][3], pA2 + ad);
                }
                #pragma unroll
                for (int g = 0; g < 2; g++) {
                    uint32_t ad = (wn * 32 + g * 16 + lrow) * ROWB + lcol + kb;
                    ldsm4(b1r[g][0], b1r[g][1], b1r[g][2], b1r[g][3], pB1 + ad);
                    ldsm4(b2r[g][0], b2r[g][1], b2r[g][2], b2r[g][3], pB2 + ad);
                }
                #pragma unroll
                for (int f = 0; f < 4; f++)
                    #pragma unroll
                    for (int g = 0; g < 2; g++)
                        #pragma unroll
                        for (int h = 0; h < 2; h++) {
                            float* d = acc[f][g*2+h];
                            mma16816(d, a1[f], b1r[g][0+h], b1r[g][2+h]);
                            mma16816(d, a1[f], b2r[g][0+h], b2r[g][2+h]);
                            mma16816(d, a2[f], b1r[g][0+h], b1r[g][2+h]);
                        }
            }
            BAR_ARRIVE(3 + bs);              // signal EMPTY[bs]
        }
    }

    __syncthreads();

    // ---- epilogue (consumer warps hold acc) ----
    float* __restrict__ Sb = g_S + (size_t)b * NN * NN;
    const int r0 = lane >> 2;
    const int c0 = (lane & 3) * 2;
    const int wm = wid >> 2;
    const int wn = wid & 3;

    if (wid < 8) {
        #pragma unroll
        for (int f = 0; f < 4; f++) {
            const int gr = rbase + wm * 64 + f * 16 + r0;
            #pragma unroll
            for (int n = 0; n < 4; n++) {
                const int gc = cbase + wn * 32 + n * 8 + c0;
                float* d = acc[f][n];
                *(float2*)&Sb[(size_t)gr * NN + gc]       = make_float2(d[0], d[1]);
                *(float2*)&Sb[(size_t)(gr + 8) * NN + gc] = make_float2(d[2], d[3]);
            }
        }
    }

    // mirror via smem transpose (coalesced both sides)
    if (jt > it) {
        float* st = (float*)smem;            // 128 x 129 floats = 66048 B
        if (wid < 8) {
            #pragma unroll
            for (int f = 0; f < 4; f++) {
                const int sr = wm * 64 + f * 16 + r0;
                #pragma unroll
                for (int n = 0; n < 4; n++) {
                    const int sc = wn * 32 + n * 8 + c0;
                    float* d = acc[f][n];
                    st[(size_t)sr * 129 + sc]           = d[0];
                    st[(size_t)sr * 129 + sc + 1]       = d[1];
                    st[(size_t)(sr + 8) * 129 + sc]     = d[2];
                    st[(size_t)(sr + 8) * 129 + sc + 1] = d[3];
                }
            }
        }
        __syncthreads();
        if (tid < 256) {
            const int mr = tid >> 1;         // mirror row = tile column
            const int hh = tid & 1;          // 64-wide half
            float* dst = Sb + (size_t)(cbase + mr) * NN + rbase + hh * 64;
            #pragma unroll
            for (int i = 0; i < 16; i++) {
                float4 v;
                v.x = st[(size_t)(hh * 64 + i * 4 + 0) * 129 + mr];
                v.y = st[(size_t)(hh * 64 + i * 4 + 1) * 129 + mr];
                v.z = st[(size_t)(hh * 64 + i * 4 + 2) * 129 + mr];
                v.w = st[(size_t)(hh * 64 + i * 4 + 3) * 129 + mr];
                *(float4*)(dst + i * 4) = v;
            }
        }
    }
}

// ---------------------------------------------------------------------------
// Kernel B: one WARP per row; exact 32nd-largest via 2-bit radix select
// (16 iterations, 3 parallel REDUX counts each).  Emits adjacency ballot
// masks (16 words/row) + rdeg so normalize never re-reads S.
// Mask layout: word (4*j + q) bit 'lane' = (S[row, 4*(lane+32*j)+q] >= thr).
// ---------------------------------------------------------------------------
__global__ __launch_bounds__(256)
void topk_threshold_kernel()
{
    const int row  = blockIdx.x * 8 + (threadIdx.x >> 5);
    const int lane = threadIdx.x & 31;
    const float* __restrict__ Sr = g_S + (size_t)row * NN;

    uint32_t u[16];
    const float4* S4 = (const float4*)Sr;
    #pragma unroll
    for (int j = 0; j < 4; j++) {
        float4 t = S4[lane + 32 * j];
        float f[4] = {t.x, t.y, t.z, t.w};
        #pragma unroll
        for (int q = 0; q < 4; q++) {
            uint32_t s = __float_as_uint(f[q]);
            u[4*j+q] = (s & 0x80000000u) ? ~s : (s | 0x80000000u);
        }
    }

    uint32_t thr = 0;
    #pragma unroll 1
    for (int bit = 30; bit >= 0; bit -= 2) {
        const uint32_t t01 = thr | (1u << bit);
        const uint32_t t10 = thr | (2u << bit);
        const uint32_t t11 = thr | (3u << bit);
        int c01 = 0, c10 = 0, c11 = 0;
        #pragma unroll
        for (int j = 0; j < 16; j++) {
            c01 += (u[j] >= t01);
            c10 += (u[j] >= t10);
            c11 += (u[j] >= t11);
        }
        c01 = __reduce_add_sync(0xffffffffu, c01);
        c10 = __reduce_add_sync(0xffffffffu, c10);
        c11 = __reduce_add_sync(0xffffffffu, c11);
        if (c11 >= 32)      thr = t11;
        else if (c10 >= 32) thr = t10;
        else if (c01 >= 32) thr = t01;
    }

    // adjacency ballots + degree
    uint32_t m[16];
    int cnt = 0;
    #pragma unroll
    for (int j = 0; j < 16; j++) {
        m[j] = __ballot_sync(0xffffffffu, u[j] >= thr);
        cnt += __popc(m[j]);
    }

    uint32_t* __restrict__ Mr = g_mask + row * 16;
    if (lane < 16) Mr[lane] = m[lane];
    if (lane == 0) g_rdeg[row] = rsqrtf((float)cnt);
}

// ---------------------------------------------------------------------------
// Kernel C: out[b,i,j] = mask[b,i,j] ? rdeg_i * rdeg_j : 0
// Reads 2 MB of masks + rdeg instead of 67 MB of S -> pure write-bound.
// One thread per float4 of output (f = j4 index 0..127).
// ---------------------------------------------------------------------------
__global__ __launch_bounds__(256)
void normalize_kernel(float* __restrict__ out)
{
    const size_t idx = (size_t)blockIdx.x * blockDim.x + threadIdx.x;
    const int f   = (int)(idx & 127);            // float4 index within row
    const int row = (int)(idx >> 7);             // 0..BB*NN-1
    const int b   = row >> 9;

    const int j    = f >> 5;                     // which ballot group
    const int lane = f & 31;                     // bit within ballots

    const uint4 mw = *(const uint4*)(g_mask + row * 16 + 4 * j);
    const float ri = g_rdeg[row];
    const float* rj = g_rdeg + b * NN + f * 4;

    float4 o;
    o.x = ((mw.x >> lane) & 1u) ? ri * rj[0] : 0.0f;
    o.y = ((mw.y >> lane) & 1u) ? ri * rj[1] : 0.0f;
    o.z = ((mw.z >> lane) & 1u) ? ri * rj[2] : 0.0f;
    o.w = ((mw.w >> lane) & 1u) ? ri * rj[3] : 0.0f;
    ((float4*)out)[idx] = o;
}

// ---------------------------------------------------------------------------
extern "C" void kernel_launch(void* const* d_in, const int* in_sizes, int n_in,
                              void* d_out, int out_size)
{
    const float* x = (const float*)d_in[0];
    float* out = (float*)d_out;

    cudaFuncSetAttribute(gemm_ws_kernel,
                         cudaFuncAttributeMaxDynamicSharedMemorySize, SMEM_TOTAL);

    dim3 gGemm(10, BB);
    gemm_ws_kernel<<<gGemm, NTHR, SMEM_TOTAL>>>(x);

    topk_threshold_kernel<<<BB * NN / 8, 256>>>();

    const int n4 = BB * NN * NN / 4;
    normalize_kernel<<<n4 / 256, 256>>>(out);
}

// round 11
// speedup vs baseline: 1.3125x; 1.0283x over previous
#include <cuda_runtime.h>
#include <cuda_fp16.h>
#include <cstdint>

#define BB 64
#define NN 512
#define CC 1024
#define KC 64
#define NCH (CC/KC)          // 16 k-chunks

// Scratch (allocation-free rule: __device__ globals)
__device__ float g_S[(size_t)BB * NN * NN];      // 67 MB gram matrices
__device__ uint32_t g_mask[BB * NN * 16];        // 2 MB adjacency ballots
__device__ float g_rdeg[BB * NN];

// smem: 4 planes per buffer, 128 rows x 64 halves, row stride 144 B.
#define ROWB   144
#define TILE_B (128 * ROWB)          // 18432
#define BUF_B  (4 * TILE_B)          // 73728
#define SMEM_TOTAL (2 * BUF_B)       // 147456

#define NTHR 384                     // 8 MMA warps + 4 producer warps

// named barriers: FULL0=1, FULL1=2, EMPTY0=3, EMPTY1=4
#define BAR_SYNC(id)   asm volatile("bar.sync %0, %1;"   :: "r"(id), "n"(NTHR) : "memory")
#define BAR_ARRIVE(id) asm volatile("bar.arrive %0, %1;" :: "r"(id), "n"(NTHR) : "memory")

__device__ __forceinline__ uint32_t smem_u32(const void* p) {
    uint32_t a;
    asm("{ .reg .u64 t; cvta.to.shared.u64 t, %1; cvt.u32.u64 %0, t; }"
        : "=r"(a) : "l"(p));
    return a;
}
__device__ __forceinline__ void ldsm4(uint32_t& r0, uint32_t& r1,
                                      uint32_t& r2, uint32_t& r3, uint32_t a) {
    asm volatile("ldmatrix.sync.aligned.m8n8.x4.shared.b16 {%0,%1,%2,%3}, [%4];"
                 : "=r"(r0), "=r"(r1), "=r"(r2), "=r"(r3) : "r"(a));
}
__device__ __forceinline__ void mma16816(float* d, const uint32_t* a,
                                         uint32_t b0, uint32_t b1) {
    asm volatile(
        "mma.sync.aligned.m16n8k16.row.col.f32.f16.f16.f32 "
        "{%0,%1,%2,%3}, {%4,%5,%6,%7}, {%8,%9}, {%0,%1,%2,%3};"
        : "+f"(d[0]), "+f"(d[1]), "+f"(d[2]), "+f"(d[3])
        : "r"(a[0]), "r"(a[1]), "r"(a[2]), "r"(a[3]), "r"(b0), "r"(b1));
}
__device__ __forceinline__ uint32_t hmul2_half(uint32_t v) {
    // multiply packed half2 by 0.5 (exact exponent shift for normals)
    __half2 h = *(__half2*)&v;
    __half2 s = __floats2half2_rn(0.5f, 0.5f);
    __half2 r = __hmul2(h, s);
    return *(uint32_t*)&r;
}

// ---------------------------------------------------------------------------
// Kernel A: warp-specialized HMMA split-fp16 GEMM (R6 schedule = measured
// ceiling) + symmetric-diagonal trick:
//   off-diag tiles: S = H1 H1^T + H1 H2^T + H2 H1^T   (3 streams)
//   diag tiles:     P = (0.5 H1) H1^T + H1 H2^T ; S = P + P^T   (2 streams)
// ---------------------------------------------------------------------------
__global__ __launch_bounds__(NTHR, 1)
void gemm_ws_kernel(const float* __restrict__ X)
{
    extern __shared__ __align__(16) char smem[];
    const unsigned char ITm[10] = {0,0,0,0,1,1,1,2,2,3};
    const unsigned char JTm[10] = {0,1,2,3,1,2,3,2,3,3};
    const int it = ITm[blockIdx.x];
    const int jt = JTm[blockIdx.x];
    const int b  = blockIdx.y;
    const int rbase = it * 128;
    const int cbase = jt * 128;
    const bool diag = (it == jt);

    const int tid  = threadIdx.x;
    const int wid  = tid >> 5;
    const int lane = tid & 31;
    const uint32_t sb = smem_u32(smem);
    const float* __restrict__ Xb = X + (size_t)b * NN * CC;

    float acc[4][4][4];
    #pragma unroll
    for (int f = 0; f < 4; f++)
        #pragma unroll
        for (int n = 0; n < 4; n++)
            #pragma unroll
            for (int q = 0; q < 4; q++) acc[f][n][q] = 0.0f;

    if (wid >= 8) {
        // ---------------- producer warps ----------------
        const int ptid = tid - 256;          // 0..127
        #pragma unroll 1
        for (int c = 0; c < NCH; c++) {
            const int bs = c & 1;
            if (c >= 2) BAR_SYNC(3 + bs);    // wait EMPTY[bs]
            char* base = smem + bs * BUF_B;
            const int k0 = c * KC;
            #pragma unroll
            for (int i = 0; i < 32; i++) {
                int u  = i * 128 + ptid;     // 0..4095 16B-units
                int t  = u >> 11;            // 0=A rows, 1=B rows
                int r  = (u >> 4) & 127;
                int f4 = u & 15;
                int grow = (t ? cbase : rbase) + r;
                float4 v = *(const float4*)(Xb + (size_t)grow * CC + k0 + f4 * 4);
                __half2 a1 = __floats2half2_rn(v.x, v.y);
                __half2 b1 = __floats2half2_rn(v.z, v.w);
                float2 fa = __half22float2(a1);
                float2 fb = __half22float2(b1);
                __half2 a2 = __floats2half2_rn(v.x - fa.x, v.y - fa.y);
                __half2 b2 = __floats2half2_rn(v.z - fb.x, v.w - fb.y);
                int off = r * ROWB + f4 * 8;
                uint32_t h1lo = *(uint32_t*)&a1, h1hi = *(uint32_t*)&b1;
                uint32_t h2lo = *(uint32_t*)&a2, h2hi = *(uint32_t*)&b2;
                if (diag && t == 0) {
                    // plane0 = 0.5*H1, plane1 = H1
                    *(uint2*)(base + 0 * TILE_B + off) =
                        make_uint2(hmul2_half(h1lo), hmul2_half(h1hi));
                    *(uint2*)(base + 1 * TILE_B + off) = make_uint2(h1lo, h1hi);
                } else {
                    *(uint2*)(base + (t*2+0) * TILE_B + off) = make_uint2(h1lo, h1hi);
                    *(uint2*)(base + (t*2+1) * TILE_B + off) = make_uint2(h2lo, h2hi);
                }
            }
            BAR_ARRIVE(1 + bs);              // signal FULL[bs]
        }
    } else {
        // ---------------- MMA consumer warps ----------------
        const int wm = wid >> 2;             // 0..1  -> 64-row slab
        const int wn = wid & 3;              // 0..3  -> 32-col slab
        const int lrow = lane & 15;
        const int lcol = (lane >> 4) * 16;

        #pragma unroll 1
        for (int c = 0; c < NCH; c++) {
            const int bs = c & 1;
            BAR_SYNC(1 + bs);                // wait FULL[bs]

            const uint32_t tb  = sb + bs * BUF_B;
            const uint32_t pA1 = tb;
            const uint32_t pA2 = tb + TILE_B;
            const uint32_t pB1 = tb + 2 * TILE_B;
            const uint32_t pB2 = tb + 3 * TILE_B;

            #pragma unroll
            for (int ks = 0; ks < 4; ks++) {
                const int kb = ks * 32;      // 16 halves = 32 B
                uint32_t a1[4][4], a2[4][4], b1r[2][4], b2r[2][4];
                #pragma unroll
                for (int f = 0; f < 4; f++) {
                    uint32_t ad = (wm * 64 + f * 16 + lrow) * ROWB + lcol + kb;
                    ldsm4(a1[f][0], a1[f][1], a1[f][2], a1[f][3], pA1 + ad);
                    ldsm4(a2[f][0], a2[f][1], a2[f][2], a2[f][3], pA2 + ad);
                }
                #pragma unroll
                for (int g = 0; g < 2; g++) {
                    uint32_t ad = (wn * 32 + g * 16 + lrow) * ROWB + lcol + kb;
                    ldsm4(b1r[g][0], b1r[g][1], b1r[g][2], b1r[g][3], pB1 + ad);
                    ldsm4(b2r[g][0], b2r[g][1], b2r[g][2], b2r[g][3], pB2 + ad);
                }
                if (diag) {
                    // P = (0.5 H1) H1^T + H1 H2^T   (a1 plane holds 0.5*H1,
                    // a2 plane holds H1)
                    #pragma unroll
                    for (int f = 0; f < 4; f++)
                        #pragma unroll
                        for (int g = 0; g < 2; g++)
                            #pragma unroll
                            for (int h = 0; h < 2; h++) {
                                float* d = acc[f][g*2+h];
                                mma16816(d, a1[f], b1r[g][0+h], b1r[g][2+h]);
                                mma16816(d, a2[f], b2r[g][0+h], b2r[g][2+h]);
                            }
                } else {
                    #pragma unroll
                    for (int f = 0; f < 4; f++)
                        #pragma unroll
                        for (int g = 0; g < 2; g++)
                            #pragma unroll
                            for (int h = 0; h < 2; h++) {
                                float* d = acc[f][g*2+h];
                                mma16816(d, a1[f], b1r[g][0+h], b1r[g][2+h]);
                                mma16816(d, a1[f], b2r[g][0+h], b2r[g][2+h]);
                                mma16816(d, a2[f], b1r[g][0+h], b1r[g][2+h]);
                            }
                }
            }
            BAR_ARRIVE(3 + bs);              // signal EMPTY[bs]
        }
    }

    __syncthreads();

    float* __restrict__ Sb = g_S + (size_t)b * NN * NN;
    const int r0 = lane >> 2;
    const int c0 = (lane & 3) * 2;
    const int wm = wid >> 2;
    const int wn = wid & 3;

    if (!diag) {
        // ---- off-diagonal epilogue: direct store + mirrored transpose ----
        if (wid < 8) {
            #pragma unroll
            for (int f = 0; f < 4; f++) {
                const int gr = rbase + wm * 64 + f * 16 + r0;
                #pragma unroll
                for (int n = 0; n < 4; n++) {
                    const int gc = cbase + wn * 32 + n * 8 + c0;
                    float* d = acc[f][n];
                    *(float2*)&Sb[(size_t)gr * NN + gc]       = make_float2(d[0], d[1]);
                    *(float2*)&Sb[(size_t)(gr + 8) * NN + gc] = make_float2(d[2], d[3]);
                }
            }
        }
        float* st = (float*)smem;            // 128 x 129 floats
        if (wid < 8) {
            #pragma unroll
            for (int f = 0; f < 4; f++) {
                const int sr = wm * 64 + f * 16 + r0;
                #pragma unroll
                for (int n = 0; n < 4; n++) {
                    const int sc = wn * 32 + n * 8 + c0;
                    float* d = acc[f][n];
                    st[(size_t)sr * 129 + sc]           = d[0];
                    st[(size_t)sr * 129 + sc + 1]       = d[1];
                    st[(size_t)(sr + 8) * 129 + sc]     = d[2];
                    st[(size_t)(sr + 8) * 129 + sc + 1] = d[3];
                }
            }
        }
        __syncthreads();
        if (tid < 256) {
            const int mr = tid >> 1;
            const int hh = tid & 1;
            float* dst = Sb + (size_t)(cbase + mr) * NN + rbase + hh * 64;
            #pragma unroll
            for (int i = 0; i < 16; i++) {
                float4 v;
                v.x = st[(size_t)(hh * 64 + i * 4 + 0) * 129 + mr];
                v.y = st[(size_t)(hh * 64 + i * 4 + 1) * 129 + mr];
                v.z = st[(size_t)(hh * 64 + i * 4 + 2) * 129 + mr];
                v.w = st[(size_t)(hh * 64 + i * 4 + 3) * 129 + mr];
                *(float4*)(dst + i * 4) = v;
            }
        }
    } else {
        // ---- diagonal epilogue: S = P + P^T via smem stage ----
        float* st = (float*)smem;            // 128 x 129 floats
        if (wid < 8) {
            #pragma unroll
            for (int f = 0; f < 4; f++) {
                const int sr = wm * 64 + f * 16 + r0;
                #pragma unroll
                for (int n = 0; n < 4; n++) {
                    const int sc = wn * 32 + n * 8 + c0;
                    float* d = acc[f][n];
                    st[(size_t)sr * 129 + sc]           = d[0];
                    st[(size_t)sr * 129 + sc + 1]       = d[1];
                    st[(size_t)(sr + 8) * 129 + sc]     = d[2];
                    st[(size_t)(sr + 8) * 129 + sc + 1] = d[3];
                }
            }
        }
        __syncthreads();
        if (tid < 256) {
            const int row = tid >> 1;
            const int hh  = tid & 1;
            float* dst = Sb + (size_t)(rbase + row) * NN + cbase + hh * 64;
            #pragma unroll
            for (int i = 0; i < 16; i++) {
                float4 v;
                #pragma unroll
                for (int q = 0; q < 4; q++) {
                    const int cc2 = hh * 64 + i * 4 + q;
                    ((float*)&v)[q] = st[(size_t)row * 129 + cc2]
                                    + st[(size_t)cc2 * 129 + row];
                }
                *(float4*)(dst + i * 4) = v;
            }
        }
    }
}

// ---------------------------------------------------------------------------
// Kernel B: one WARP per row; exact 32nd-largest via 1-bit radix select
// (proven fastest); emits adjacency ballots + rdeg.
// Mask layout: word (4*j + q) bit 'lane' = (S[row, 4*(lane+32*j)+q] >= thr).
// ---------------------------------------------------------------------------
__global__ __launch_bounds__(256)
void topk_threshold_kernel()
{
    const int row  = blockIdx.x * 8 + (threadIdx.x >> 5);
    const int lane = threadIdx.x & 31;
    const float* __restrict__ Sr = g_S + (size_t)row * NN;

    uint32_t u[16];
    const float4* S4 = (const float4*)Sr;
    #pragma unroll
    for (int j = 0; j < 4; j++) {
        float4 t = S4[lane + 32 * j];
        float f[4] = {t.x, t.y, t.z, t.w};
        #pragma unroll
        for (int q = 0; q < 4; q++) {
            uint32_t s = __float_as_uint(f[q]);
            u[4*j+q] = (s & 0x80000000u) ? ~s : (s | 0x80000000u);
        }
    }

    uint32_t thr = 0;
    #pragma unroll 1
    for (int bit = 31; bit >= 0; bit--) {
        const uint32_t test = thr | (1u << bit);
        int c = 0;
        #pragma unroll
        for (int j = 0; j < 16; j++) c += (u[j] >= test);
        c = __reduce_add_sync(0xffffffffu, c);
        if (c >= 32) thr = test;
    }

    uint32_t m[16];
    int cnt = 0;
    #pragma unroll
    for (int j = 0; j < 16; j++) {
        m[j] = __ballot_sync(0xffffffffu, u[j] >= thr);
        cnt += __popc(m[j]);
    }

    uint32_t* __restrict__ Mr = g_mask + row * 16;
    if (lane < 16) Mr[lane] = m[lane];
    if (lane == 0) g_rdeg[row] = rsqrtf((float)cnt);
}

// ---------------------------------------------------------------------------
// Kernel C: out[b,i,j] = mask[b,i,j] ? rdeg_i * rdeg_j : 0
// Reads 2 MB of masks + rdeg instead of 67 MB of S -> write-bound.
// ---------------------------------------------------------------------------
__global__ __launch_bounds__(256)
void normalize_kernel(float* __restrict__ out)
{
    const size_t idx = (size_t)blockIdx.x * blockDim.x + threadIdx.x;
    const int f   = (int)(idx & 127);            // float4 index within row
    const int row = (int)(idx >> 7);             // 0..BB*NN-1
    const int b   = row >> 9;

    const int j    = f >> 5;
    const int lane = f & 31;

    const uint4 mw = *(const uint4*)(g_mask + row * 16 + 4 * j);
    const float ri = g_rdeg[row];
    const float* rj = g_rdeg + b * NN + f * 4;

    float4 o;
    o.x = ((mw.x >> lane) & 1u) ? ri * rj[0] : 0.0f;
    o.y = ((mw.y >> lane) & 1u) ? ri * rj[1] : 0.0f;
    o.z = ((mw.z >> lane) & 1u) ? ri * rj[2] : 0.0f;
    o.w = ((mw.w >> lane) & 1u) ? ri * rj[3] : 0.0f;
    ((float4*)out)[idx] = o;
}

// ---------------------------------------------------------------------------
extern "C" void kernel_launch(void* const* d_in, const int* in_sizes, int n_in,
                              void* d_out, int out_size)
{
    const float* x = (const float*)d_in[0];
    float* out = (float*)d_out;

    cudaFuncSetAttribute(gemm_ws_kernel,
                         cudaFuncAttributeMaxDynamicSharedMemorySize, SMEM_TOTAL);

    dim3 gGemm(10, BB);
    gemm_ws_kernel<<<gGemm, NTHR, SMEM_TOTAL>>>(x);

    topk_threshold_kernel<<<BB * NN / 8, 256>>>();

    const int n4 = BB * NN * NN / 4;
    normalize_kernel<<<n4 / 256, 256>>>(out);
}

// round 12
// speedup vs baseline: 1.3532x; 1.0310x over previous
#include <cuda_runtime.h>
#include <cuda_fp16.h>
#include <cstdint>

#define BB 64
#define NN 512
#define CC 1024
#define KC 64
#define NCH (CC/KC)          // 16 k-chunks
#define NCTA 128             // persistent CTAs
#define TPC  5               // tiles per CTA (128*5 = 640 = 10 pairs * 64 batches)

// Scratch (allocation-free rule: __device__ globals)
__device__ float g_S[(size_t)BB * NN * NN];      // 67 MB gram matrices
__device__ uint32_t g_mask[BB * NN * 16];        // 2 MB adjacency ballots
__device__ float g_rdeg[BB * NN];

// smem: 4 planes per buffer, 128 rows x 64 halves, row stride 144 B.
#define ROWB   144
#define TILE_B (128 * ROWB)          // 18432
#define BUF_B  (4 * TILE_B)          // 73728
#define SMEM_TOTAL (2 * BUF_B)       // 147456

#define NTHR 384                     // 8 MMA warps + 4 producer warps

// named barriers: FULL0=1, FULL1=2, EMPTY0=3, EMPTY1=4
#define BAR_SYNC(id)   asm volatile("bar.sync %0, %1;"   :: "r"(id), "n"(NTHR) : "memory")
#define BAR_ARRIVE(id) asm volatile("bar.arrive %0, %1;" :: "r"(id), "n"(NTHR) : "memory")

__device__ __forceinline__ uint32_t smem_u32(const void* p) {
    uint32_t a;
    asm("{ .reg .u64 t; cvta.to.shared.u64 t, %1; cvt.u32.u64 %0, t; }"
        : "=r"(a) : "l"(p));
    return a;
}
__device__ __forceinline__ void ldsm4(uint32_t& r0, uint32_t& r1,
                                      uint32_t& r2, uint32_t& r3, uint32_t a) {
    asm volatile("ldmatrix.sync.aligned.m8n8.x4.shared.b16 {%0,%1,%2,%3}, [%4];"
                 : "=r"(r0), "=r"(r1), "=r"(r2), "=r"(r3) : "r"(a));
}
__device__ __forceinline__ void mma16816(float* d, const uint32_t* a,
                                         uint32_t b0, uint32_t b1) {
    asm volatile(
        "mma.sync.aligned.m16n8k16.row.col.f32.f16.f16.f32 "
        "{%0,%1,%2,%3}, {%4,%5,%6,%7}, {%8,%9}, {%0,%1,%2,%3};"
        : "+f"(d[0]), "+f"(d[1]), "+f"(d[2]), "+f"(d[3])
        : "r"(a[0]), "r"(a[1]), "r"(a[2]), "r"(a[3]), "r"(b0), "r"(b1));
}
__device__ __forceinline__ uint32_t hmul2_half(uint32_t v) {
    __half2 h = *(__half2*)&v;
    __half2 s = __floats2half2_rn(0.5f, 0.5f);
    __half2 r = __hmul2(h, s);
    return *(uint32_t*)&r;
}

// ---------------------------------------------------------------------------
// Kernel A: persistent warp-specialized HMMA split-fp16 GEMM.
//   off-diag tiles: S = H1 H1^T + H1 H2^T + H2 H1^T    (3 streams)
//   diag tiles:     P = (0.5 H1) H1^T + H1 H2^T ; S = P + P^T  (2 streams)
// 128 CTAs x 5 tiles each (stride-128 tile ids -> every CTA gets exactly
// 2 diag + 3 off-diag: uniform 4.33-unit load, single wave, no tail).
// Barrier pairing exact per tile: FULL 16/16, EMPTY 14/14; inter-tile
// __syncthreads protects buffer + epilogue smem reuse.
// ---------------------------------------------------------------------------
__global__ __launch_bounds__(NTHR, 1)
void gemm_ws_kernel(const float* __restrict__ X)
{
    extern __shared__ __align__(16) char smem[];
    const unsigned char ITm[10] = {0,0,0,0,1,1,1,2,2,3};
    const unsigned char JTm[10] = {0,1,2,3,1,2,3,2,3,3};

    const int tid  = threadIdx.x;
    const int wid  = tid >> 5;
    const int lane = tid & 31;
    const uint32_t sb = smem_u32(smem);

    #pragma unroll 1
    for (int tk = 0; tk < TPC; tk++) {
        const int g    = blockIdx.x + NCTA * tk;   // global tile id
        const int pair = g % 10;
        const int b    = g / 10;
        const int it = ITm[pair];
        const int jt = JTm[pair];
        const int rbase = it * 128;
        const int cbase = jt * 128;
        const bool diag = (it == jt);
        const float* __restrict__ Xb = X + (size_t)b * NN * CC;

        float acc[4][4][4];
        #pragma unroll
        for (int f = 0; f < 4; f++)
            #pragma unroll
            for (int n = 0; n < 4; n++)
                #pragma unroll
                for (int q = 0; q < 4; q++) acc[f][n][q] = 0.0f;

        if (wid >= 8) {
            // ---------------- producer warps ----------------
            const int ptid = tid - 256;          // 0..127
            #pragma unroll 1
            for (int c = 0; c < NCH; c++) {
                const int bs = c & 1;
                if (c >= 2) BAR_SYNC(3 + bs);    // wait EMPTY[bs]
                char* base = smem + bs * BUF_B;
                const int k0 = c * KC;
                #pragma unroll
                for (int i = 0; i < 32; i++) {
                    int u  = i * 128 + ptid;     // 0..4095 16B-units
                    int t  = u >> 11;            // 0=A rows, 1=B rows
                    int r  = (u >> 4) & 127;
                    int f4 = u & 15;
                    int grow = (t ? cbase : rbase) + r;
                    float4 v = *(const float4*)(Xb + (size_t)grow * CC + k0 + f4 * 4);
                    __half2 a1 = __floats2half2_rn(v.x, v.y);
                    __half2 b1 = __floats2half2_rn(v.z, v.w);
                    float2 fa = __half22float2(a1);
                    float2 fb = __half22float2(b1);
                    __half2 a2 = __floats2half2_rn(v.x - fa.x, v.y - fa.y);
                    __half2 b2 = __floats2half2_rn(v.z - fb.x, v.w - fb.y);
                    int off = r * ROWB + f4 * 8;
                    uint32_t h1lo = *(uint32_t*)&a1, h1hi = *(uint32_t*)&b1;
                    uint32_t h2lo = *(uint32_t*)&a2, h2hi = *(uint32_t*)&b2;
                    if (diag && t == 0) {
                        // plane0 = 0.5*H1, plane1 = H1
                        *(uint2*)(base + 0 * TILE_B + off) =
                            make_uint2(hmul2_half(h1lo), hmul2_half(h1hi));
                        *(uint2*)(base + 1 * TILE_B + off) = make_uint2(h1lo, h1hi);
                    } else {
                        *(uint2*)(base + (t*2+0) * TILE_B + off) = make_uint2(h1lo, h1hi);
                        *(uint2*)(base + (t*2+1) * TILE_B + off) = make_uint2(h2lo, h2hi);
                    }
                }
                BAR_ARRIVE(1 + bs);              // signal FULL[bs]
            }
        } else {
            // ---------------- MMA consumer warps ----------------
            const int wm = wid >> 2;             // 0..1  -> 64-row slab
            const int wn = wid & 3;              // 0..3  -> 32-col slab
            const int lrow = lane & 15;
            const int lcol = (lane >> 4) * 16;

            if (!diag) {
                #pragma unroll 1
                for (int c = 0; c < NCH; c++) {
                    const int bs = c & 1;
                    BAR_SYNC(1 + bs);            // wait FULL[bs]
                    const uint32_t tb  = sb + bs * BUF_B;
                    const uint32_t pA1 = tb;
                    const uint32_t pA2 = tb + TILE_B;
                    const uint32_t pB1 = tb + 2 * TILE_B;
                    const uint32_t pB2 = tb + 3 * TILE_B;
                    #pragma unroll
                    for (int ks = 0; ks < 4; ks++) {
                        const int kb = ks * 32;
                        uint32_t a1[4][4], a2[4][4], b1r[2][4], b2r[2][4];
                        #pragma unroll
                        for (int f = 0; f < 4; f++) {
                            uint32_t ad = (wm * 64 + f * 16 + lrow) * ROWB + lcol + kb;
                            ldsm4(a1[f][0], a1[f][1], a1[f][2], a1[f][3], pA1 + ad);
                            ldsm4(a2[f][0], a2[f][1], a2[f][2], a2[f][3], pA2 + ad);
                        }
                        #pragma unroll
                        for (int gg = 0; gg < 2; gg++) {
                            uint32_t ad = (wn * 32 + gg * 16 + lrow) * ROWB + lcol + kb;
                            ldsm4(b1r[gg][0], b1r[gg][1], b1r[gg][2], b1r[gg][3], pB1 + ad);
                            ldsm4(b2r[gg][0], b2r[gg][1], b2r[gg][2], b2r[gg][3], pB2 + ad);
                        }
                        #pragma unroll
                        for (int f = 0; f < 4; f++)
                            #pragma unroll
                            for (int gg = 0; gg < 2; gg++)
                                #pragma unroll
                                for (int h = 0; h < 2; h++) {
                                    float* d = acc[f][gg*2+h];
                                    mma16816(d, a1[f], b1r[gg][0+h], b1r[gg][2+h]);
                                    mma16816(d, a1[f], b2r[gg][0+h], b2r[gg][2+h]);
                                    mma16816(d, a2[f], b1r[gg][0+h], b1r[gg][2+h]);
                                }
                    }
                    if (c < NCH - 2) BAR_ARRIVE(3 + bs);   // signal EMPTY[bs]
                }
            } else {
                #pragma unroll 1
                for (int c = 0; c < NCH; c++) {
                    const int bs = c & 1;
                    BAR_SYNC(1 + bs);            // wait FULL[bs]
                    const uint32_t tb  = sb + bs * BUF_B;
                    const uint32_t pA1 = tb;             // 0.5*H1
                    const uint32_t pA2 = tb + TILE_B;    // H1
                    const uint32_t pB1 = tb + 2 * TILE_B;
                    const uint32_t pB2 = tb + 3 * TILE_B;
                    #pragma unroll
                    for (int ks = 0; ks < 4; ks++) {
                        const int kb = ks * 32;
                        uint32_t a1[4][4], a2[4][4], b1r[2][4], b2r[2][4];
                        #pragma unroll
                        for (int f = 0; f < 4; f++) {
                            uint32_t ad = (wm * 64 + f * 16 + lrow) * ROWB + lcol + kb;
                            ldsm4(a1[f][0], a1[f][1], a1[f][2], a1[f][3], pA1 + ad);
                            ldsm4(a2[f][0], a2[f][1], a2[f][2], a2[f][3], pA2 + ad);
                        }
                        #pragma unroll
                        for (int gg = 0; gg < 2; gg++) {
                            uint32_t ad = (wn * 32 + gg * 16 + lrow) * ROWB + lcol + kb;
                            ldsm4(b1r[gg][0], b1r[gg][1], b1r[gg][2], b1r[gg][3], pB1 + ad);
                            ldsm4(b2r[gg][0], b2r[gg][1], b2r[gg][2], b2r[gg][3], pB2 + ad);
                        }
                        // P = (0.5 H1) H1^T + H1 H2^T
                        #pragma unroll
                        for (int f = 0; f < 4; f++)
                            #pragma unroll
                            for (int gg = 0; gg < 2; gg++)
                                #pragma unroll
                                for (int h = 0; h < 2; h++) {
                                    float* d = acc[f][gg*2+h];
                                    mma16816(d, a1[f], b1r[gg][0+h], b1r[gg][2+h]);
                                    mma16816(d, a2[f], b2r[gg][0+h], b2r[gg][2+h]);
                                }
                    }
                    if (c < NCH - 2) BAR_ARRIVE(3 + bs);   // signal EMPTY[bs]
                }
            }
        }

        __syncthreads();

        // ---- per-tile epilogue ----
        float* __restrict__ Sb = g_S + (size_t)b * NN * NN;
        const int r0 = lane >> 2;
        const int c0 = (lane & 3) * 2;
        const int wm = wid >> 2;
        const int wn = wid & 3;
        float* st = (float*)smem;            // 128 x 129 floats

        if (!diag) {
            if (wid < 8) {
                #pragma unroll
                for (int f = 0; f < 4; f++) {
                    const int gr = rbase + wm * 64 + f * 16 + r0;
                    #pragma unroll
                    for (int n = 0; n < 4; n++) {
                        const int gc = cbase + wn * 32 + n * 8 + c0;
                        float* d = acc[f][n];
                        *(float2*)&Sb[(size_t)gr * NN + gc]       = make_float2(d[0], d[1]);
                        *(float2*)&Sb[(size_t)(gr + 8) * NN + gc] = make_float2(d[2], d[3]);
                    }
                }
                #pragma unroll
                for (int f = 0; f < 4; f++) {
                    const int sr = wm * 64 + f * 16 + r0;
                    #pragma unroll
                    for (int n = 0; n < 4; n++) {
                        const int sc = wn * 32 + n * 8 + c0;
                        float* d = acc[f][n];
                        st[(size_t)sr * 129 + sc]           = d[0];
                        st[(size_t)sr * 129 + sc + 1]       = d[1];
                        st[(size_t)(sr + 8) * 129 + sc]     = d[2];
                        st[(size_t)(sr + 8) * 129 + sc + 1] = d[3];
                    }
                }
            }
            __syncthreads();
            if (tid < 256) {
                const int mr = tid >> 1;
                const int hh = tid & 1;
                float* dst = Sb + (size_t)(cbase + mr) * NN + rbase + hh * 64;
                #pragma unroll
                for (int i = 0; i < 16; i++) {
                    float4 v;
                    v.x = st[(size_t)(hh * 64 + i * 4 + 0) * 129 + mr];
                    v.y = st[(size_t)(hh * 64 + i * 4 + 1) * 129 + mr];
                    v.z = st[(size_t)(hh * 64 + i * 4 + 2) * 129 + mr];
                    v.w = st[(size_t)(hh * 64 + i * 4 + 3) * 129 + mr];
                    *(float4*)(dst + i * 4) = v;
                }
            }
        } else {
            if (wid < 8) {
                #pragma unroll
                for (int f = 0; f < 4; f++) {
                    const int sr = wm * 64 + f * 16 + r0;
                    #pragma unroll
                    for (int n = 0; n < 4; n++) {
                        const int sc = wn * 32 + n * 8 + c0;
                        float* d = acc[f][n];
                        st[(size_t)sr * 129 + sc]           = d[0];
                        st[(size_t)sr * 129 + sc + 1]       = d[1];
                        st[(size_t)(sr + 8) * 129 + sc]     = d[2];
                        st[(size_t)(sr + 8) * 129 + sc + 1] = d[3];
                    }
                }
            }
            __syncthreads();
            if (tid < 256) {
                const int row = tid >> 1;
                const int hh  = tid & 1;
                float* dst = Sb + (size_t)(rbase + row) * NN + cbase + hh * 64;
                #pragma unroll
                for (int i = 0; i < 16; i++) {
                    float4 v;
                    #pragma unroll
                    for (int q = 0; q < 4; q++) {
                        const int cc2 = hh * 64 + i * 4 + q;
                        ((float*)&v)[q] = st[(size_t)row * 129 + cc2]
                                        + st[(size_t)cc2 * 129 + row];
                    }
                    *(float4*)(dst + i * 4) = v;
                }
            }
        }
        __syncthreads();   // smem free before next tile's producers start
    }
}

// ---------------------------------------------------------------------------
// Kernel B: one WARP per row; exact 32nd-largest via 1-bit radix select;
// emits adjacency ballots + rdeg.
// ---------------------------------------------------------------------------
__global__ __launch_bounds__(256)
void topk_threshold_kernel()
{
    const int row  = blockIdx.x * 8 + (threadIdx.x >> 5);
    const int lane = threadIdx.x & 31;
    const float* __restrict__ Sr = g_S + (size_t)row * NN;

    uint32_t u[16];
    const float4* S4 = (const float4*)Sr;
    #pragma unroll
    for (int j = 0; j < 4; j++) {
        float4 t = S4[lane + 32 * j];
        float f[4] = {t.x, t.y, t.z, t.w};
        #pragma unroll
        for (int q = 0; q < 4; q++) {
            uint32_t s = __float_as_uint(f[q]);
            u[4*j+q] = (s & 0x80000000u) ? ~s : (s | 0x80000000u);
        }
    }

    uint32_t thr = 0;
    #pragma unroll 1
    for (int bit = 31; bit >= 0; bit--) {
        const uint32_t test = thr | (1u << bit);
        int c = 0;
        #pragma unroll
        for (int j = 0; j < 16; j++) c += (u[j] >= test);
        c = __reduce_add_sync(0xffffffffu, c);
        if (c >= 32) thr = test;
    }

    uint32_t m[16];
    int cnt = 0;
    #pragma unroll
    for (int j = 0; j < 16; j++) {
        m[j] = __ballot_sync(0xffffffffu, u[j] >= thr);
        cnt += __popc(m[j]);
    }

    uint32_t* __restrict__ Mr = g_mask + row * 16;
    if (lane < 16) Mr[lane] = m[lane];
    if (lane == 0) g_rdeg[row] = rsqrtf((float)cnt);
}

// ---------------------------------------------------------------------------
// Kernel C: out[b,i,j] = mask[b,i,j] ? rdeg_i * rdeg_j : 0   (write-bound)
// ---------------------------------------------------------------------------
__global__ __launch_bounds__(256)
void normalize_kernel(float* __restrict__ out)
{
    const size_t idx = (size_t)blockIdx.x * blockDim.x + threadIdx.x;
    const int f   = (int)(idx & 127);
    const int row = (int)(idx >> 7);
    const int b   = row >> 9;

    const int j    = f >> 5;
    const int lane = f & 31;

    const uint4 mw = *(const uint4*)(g_mask + row * 16 + 4 * j);
    const float ri = g_rdeg[row];
    const float* rj = g_rdeg + b * NN + f * 4;

    float4 o;
    o.x = ((mw.x >> lane) & 1u) ? ri * rj[0] : 0.0f;
    o.y = ((mw.y >> lane) & 1u) ? ri * rj[1] : 0.0f;
    o.z = ((mw.z >> lane) & 1u) ? ri * rj[2] : 0.0f;
    o.w = ((mw.w >> lane) & 1u) ? ri * rj[3] : 0.0f;
    ((float4*)out)[idx] = o;
}

// ---------------------------------------------------------------------------
extern "C" void kernel_launch(void* const* d_in, const int* in_sizes, int n_in,
                              void* d_out, int out_size)
{
    const float* x = (const float*)d_in[0];
    float* out = (float*)d_out;

    cudaFuncSetAttribute(gemm_ws_kernel,
                         cudaFuncAttributeMaxDynamicSharedMemorySize, SMEM_TOTAL);

    gemm_ws_kernel<<<NCTA, NTHR, SMEM_TOTAL>>>(x);

    topk_threshold_kernel<<<BB * NN / 8, 256>>>();

    const int n4 = BB * NN * NN / 4;
    normalize_kernel<<<n4 / 256, 256>>>(out);
}

// round 13
// speedup vs baseline: 1.4616x; 1.0801x over previous
#include <cuda_runtime.h>
#include <cuda_fp16.h>
#include <cstdint>

#define BB 64
#define NN 512
#define CC 1024
#define KC 64
#define NCH (CC/KC)          // 16 k-chunks

// Scratch (allocation-free rule: __device__ globals)
__device__ float g_S[(size_t)BB * NN * NN];      // 67 MB gram matrices
__device__ uint32_t g_mask[BB * NN * 16];        // 2 MB adjacency ballots
__device__ float g_rdeg[BB * NN];

// smem: 4 planes per buffer (A1,A2,B1,B2), 128 rows x 64 halves,
// padded row stride 144 B for conflict-free ldmatrix.
#define ROWB   144
#define TILE_B (128 * ROWB)          // 18432
#define BUF_B  (4 * TILE_B)          // 73728
#define SMEM_TOTAL (2 * BUF_B)       // 147456

#define NTHR 384                     // 8 MMA warps + 4 producer warps

// named barriers: FULL0=1, FULL1=2, EMPTY0=3, EMPTY1=4
#define BAR_SYNC(id)   asm volatile("bar.sync %0, %1;"   :: "r"(id), "n"(NTHR) : "memory")
#define BAR_ARRIVE(id) asm volatile("bar.arrive %0, %1;" :: "r"(id), "n"(NTHR) : "memory")

__device__ __forceinline__ uint32_t smem_u32(const void* p) {
    uint32_t a;
    asm("{ .reg .u64 t; cvta.to.shared.u64 t, %1; cvt.u32.u64 %0, t; }"
        : "=r"(a) : "l"(p));
    return a;
}
__device__ __forceinline__ void ldsm4(uint32_t& r0, uint32_t& r1,
                                      uint32_t& r2, uint32_t& r3, uint32_t a) {
    asm volatile("ldmatrix.sync.aligned.m8n8.x4.shared.b16 {%0,%1,%2,%3}, [%4];"
                 : "=r"(r0), "=r"(r1), "=r"(r2), "=r"(r3) : "r"(a));
}
__device__ __forceinline__ void mma16816(float* d, const uint32_t* a,
                                         uint32_t b0, uint32_t b1) {
    asm volatile(
        "mma.sync.aligned.m16n8k16.row.col.f32.f16.f16.f32 "
        "{%0,%1,%2,%3}, {%4,%5,%6,%7}, {%8,%9}, {%0,%1,%2,%3};"
        : "+f"(d[0]), "+f"(d[1]), "+f"(d[2]), "+f"(d[3])
        : "r"(a[0]), "r"(a[1]), "r"(a[2]), "r"(a[3]), "r"(b0), "r"(b1));
}

// ---------------------------------------------------------------------------
// Kernel A: warp-specialized HMMA split-fp16 GEMM (R6 configuration =
// measured legacy-HMMA ceiling, 223.2 us reproduced twice).
// S = H1 H1^T + H1 H2^T + H2 H1^T, fp32 accumulation (exact to ~2^-22).
// ---------------------------------------------------------------------------
__global__ __launch_bounds__(NTHR, 1)
void gemm_ws_kernel(const float* __restrict__ X)
{
    extern __shared__ __align__(16) char smem[];
    const unsigned char ITm[10] = {0,0,0,0,1,1,1,2,2,3};
    const unsigned char JTm[10] = {0,1,2,3,1,2,3,2,3,3};
    const int it = ITm[blockIdx.x];
    const int jt = JTm[blockIdx.x];
    const int b  = blockIdx.y;
    const int rbase = it * 128;
    const int cbase = jt * 128;

    const int tid  = threadIdx.x;
    const int wid  = tid >> 5;
    const int lane = tid & 31;
    const uint32_t sb = smem_u32(smem);
    const float* __restrict__ Xb = X + (size_t)b * NN * CC;

    float acc[4][4][4];
    #pragma unroll
    for (int f = 0; f < 4; f++)
        #pragma unroll
        for (int n = 0; n < 4; n++)
            #pragma unroll
            for (int q = 0; q < 4; q++) acc[f][n][q] = 0.0f;

    if (wid >= 8) {
        // ---------------- producer warps ----------------
        const int ptid = tid - 256;          // 0..127
        #pragma unroll 1
        for (int c = 0; c < NCH; c++) {
            const int bs = c & 1;
            if (c >= 2) BAR_SYNC(3 + bs);    // wait EMPTY[bs]
            char* base = smem + bs * BUF_B;
            const int k0 = c * KC;
            #pragma unroll
            for (int i = 0; i < 32; i++) {
                int u  = i * 128 + ptid;     // 0..4095 16B-units
                int t  = u >> 11;            // 0=A rows, 1=B rows
                int r  = (u >> 4) & 127;
                int f4 = u & 15;
                int grow = (t ? cbase : rbase) + r;
                float4 v = *(const float4*)(Xb + (size_t)grow * CC + k0 + f4 * 4);
                __half2 a1 = __floats2half2_rn(v.x, v.y);
                __half2 b1 = __floats2half2_rn(v.z, v.w);
                float2 fa = __half22float2(a1);
                float2 fb = __half22float2(b1);
                __half2 a2 = __floats2half2_rn(v.x - fa.x, v.y - fa.y);
                __half2 b2 = __floats2half2_rn(v.z - fb.x, v.w - fb.y);
                int off = r * ROWB + f4 * 8;
                *(uint2*)(base + (t*2+0) * TILE_B + off) =
                    make_uint2(*(uint32_t*)&a1, *(uint32_t*)&b1);
                *(uint2*)(base + (t*2+1) * TILE_B + off) =
                    make_uint2(*(uint32_t*)&a2, *(uint32_t*)&b2);
            }
            BAR_ARRIVE(1 + bs);              // signal FULL[bs]
        }
    } else {
        // ---------------- MMA consumer warps ----------------
        const int wm = wid >> 2;             // 0..1  -> 64-row slab
        const int wn = wid & 3;              // 0..3  -> 32-col slab
        const int lrow = lane & 15;
        const int lcol = (lane >> 4) * 16;

        #pragma unroll 1
        for (int c = 0; c < NCH; c++) {
            const int bs = c & 1;
            BAR_SYNC(1 + bs);                // wait FULL[bs]

            const uint32_t tb  = sb + bs * BUF_B;
            const uint32_t pA1 = tb;
            const uint32_t pA2 = tb + TILE_B;
            const uint32_t pB1 = tb + 2 * TILE_B;
            const uint32_t pB2 = tb + 3 * TILE_B;

            #pragma unroll
            for (int ks = 0; ks < 4; ks++) {
                const int kb = ks * 32;      // 16 halves = 32 B
                uint32_t a1[4][4], a2[4][4], b1r[2][4], b2r[2][4];
                #pragma unroll
                for (int f = 0; f < 4; f++) {
                    uint32_t ad = (wm * 64 + f * 16 + lrow) * ROWB + lcol + kb;
                    ldsm4(a1[f][0], a1[f][1], a1[f][2], a1[f][3], pA1 + ad);
                    ldsm4(a2[f][0], a2[f][1], a2[f][2], a2[f][3], pA2 + ad);
                }
                #pragma unroll
                for (int g = 0; g < 2; g++) {
                    uint32_t ad = (wn * 32 + g * 16 + lrow) * ROWB + lcol + kb;
                    ldsm4(b1r[g][0], b1r[g][1], b1r[g][2], b1r[g][3], pB1 + ad);
                    ldsm4(b2r[g][0], b2r[g][1], b2r[g][2], b2r[g][3], pB2 + ad);
                }
                #pragma unroll
                for (int f = 0; f < 4; f++)
                    #pragma unroll
                    for (int g = 0; g < 2; g++)
                        #pragma unroll
                        for (int h = 0; h < 2; h++) {
                            float* d = acc[f][g*2+h];
                            mma16816(d, a1[f], b1r[g][0+h], b1r[g][2+h]);
                            mma16816(d, a1[f], b2r[g][0+h], b2r[g][2+h]);
                            mma16816(d, a2[f], b1r[g][0+h], b1r[g][2+h]);
                        }
            }
            BAR_ARRIVE(3 + bs);              // signal EMPTY[bs]
        }
    }

    __syncthreads();

    // ---- epilogue (consumer warps hold acc) ----
    float* __restrict__ Sb = g_S + (size_t)b * NN * NN;
    const int r0 = lane >> 2;
    const int c0 = (lane & 3) * 2;
    const int wm = wid >> 2;
    const int wn = wid & 3;

    if (wid < 8) {
        #pragma unroll
        for (int f = 0; f < 4; f++) {
            const int gr = rbase + wm * 64 + f * 16 + r0;
            #pragma unroll
            for (int n = 0; n < 4; n++) {
                const int gc = cbase + wn * 32 + n * 8 + c0;
                float* d = acc[f][n];
                *(float2*)&Sb[(size_t)gr * NN + gc]       = make_float2(d[0], d[1]);
                *(float2*)&Sb[(size_t)(gr + 8) * NN + gc] = make_float2(d[2], d[3]);
            }
        }
    }

    // mirror via smem transpose (coalesced both sides)
    if (jt > it) {
        float* st = (float*)smem;            // 128 x 129 floats
        if (wid < 8) {
            #pragma unroll
            for (int f = 0; f < 4; f++) {
                const int sr = wm * 64 + f * 16 + r0;
                #pragma unroll
                for (int n = 0; n < 4; n++) {
                    const int sc = wn * 32 + n * 8 + c0;
                    float* d = acc[f][n];
                    st[(size_t)sr * 129 + sc]           = d[0];
                    st[(size_t)sr * 129 + sc + 1]       = d[1];
                    st[(size_t)(sr + 8) * 129 + sc]     = d[2];
                    st[(size_t)(sr + 8) * 129 + sc + 1] = d[3];
                }
            }
        }
        __syncthreads();
        if (tid < 256) {
            const int mr = tid >> 1;
            const int hh = tid & 1;
            float* dst = Sb + (size_t)(cbase + mr) * NN + rbase + hh * 64;
            #pragma unroll
            for (int i = 0; i < 16; i++) {
                float4 v;
                v.x = st[(size_t)(hh * 64 + i * 4 + 0) * 129 + mr];
                v.y = st[(size_t)(hh * 64 + i * 4 + 1) * 129 + mr];
                v.z = st[(size_t)(hh * 64 + i * 4 + 2) * 129 + mr];
                v.w = st[(size_t)(hh * 64 + i * 4 + 3) * 129 + mr];
                *(float4*)(dst + i * 4) = v;
            }
        }
    }
}

// ---------------------------------------------------------------------------
// Kernel B: one WARP per row; exact 32nd-largest via prefix-skip 1-bit radix
// with per-lane top-4 fast counting (exact rare-path rescan).
//  - monotone key map: float -> uint32, order-preserving
//  - t0 = min(lane maxes) <= thr  (every lane has >=1 value >= t0 -> cnt>=32)
//  - t2 = 2nd-largest of row >= thr; radix starts at first differing bit
//  - per iter: count via sorted top-4 regs (4 cmps); if lane's 4th >= test,
//    exact rescan of its 16 values (rare).
// Emits adjacency ballots (16 words/row) + rdeg.
// ---------------------------------------------------------------------------
__global__ __launch_bounds__(256)
void topk_threshold_kernel()
{
    const int row  = blockIdx.x * 8 + (threadIdx.x >> 5);
    const int lane = threadIdx.x & 31;
    const float* __restrict__ Sr = g_S + (size_t)row * NN;

    uint32_t u[16];
    const float4* S4 = (const float4*)Sr;
    #pragma unroll
    for (int j = 0; j < 4; j++) {
        float4 t = S4[lane + 32 * j];
        float f[4] = {t.x, t.y, t.z, t.w};
        #pragma unroll
        for (int q = 0; q < 4; q++) {
            uint32_t s = __float_as_uint(f[q]);
            u[4*j+q] = (s & 0x80000000u) ? ~s : (s | 0x80000000u);
        }
    }

    // per-lane top-4 (descending): s0 >= s1 >= s2 >= s3
    uint32_t s0 = 0, s1 = 0, s2 = 0, s3 = 0;
    #pragma unroll
    for (int j = 0; j < 16; j++) {
        uint32_t v = u[j], t;
        t = max(s0, v); v = min(s0, v); s0 = t;
        t = max(s1, v); v = min(s1, v); s1 = t;
        t = max(s2, v); v = min(s2, v); s2 = t;
        s3 = max(s3, v);
    }

    const uint32_t t0   = __reduce_min_sync(0xffffffffu, s0);  // lower bound
    const uint32_t tmax = __reduce_max_sync(0xffffffffu, s0);  // row max
    // row 2nd-largest (upper bound on thr)
    const uint32_t t2 = __reduce_max_sync(0xffffffffu, (s0 == tmax) ? s1 : s0);

    uint32_t thr;
    if (t0 >= t2) {
        thr = t0;                      // answer pinned (incl. all-equal cases)
    } else {
        const int b0 = 31 - __clz(t0 ^ t2);
        const uint32_t low = (uint32_t)(((uint64_t)2 << b0) - 1u);
        thr = t0 & ~low;               // common prefix, unknown bits zero
        #pragma unroll 1
        for (int bit = b0; bit >= 0; bit--) {
            const uint32_t test = thr | (1u << bit);
            int c = (int)(s0 >= test) + (int)(s1 >= test)
                  + (int)(s2 >= test) + (int)(s3 >= test);
            if (c == 4) {              // lane may hold >4 above test: exact rescan
                int cf = 0;
                #pragma unroll
                for (int j = 0; j < 16; j++) cf += (u[j] >= test);
                c = cf;
            }
            c = __reduce_add_sync(0xffffffffu, c);
            if (c >= 32) thr = test;
        }
    }

    // adjacency ballots + degree
    uint32_t m[16];
    int cnt = 0;
    #pragma unroll
    for (int j = 0; j < 16; j++) {
        m[j] = __ballot_sync(0xffffffffu, u[j] >= thr);
        cnt += __popc(m[j]);
    }

    uint32_t* __restrict__ Mr = g_mask + row * 16;
    if (lane < 16) Mr[lane] = m[lane];
    if (lane == 0) g_rdeg[row] = rsqrtf((float)cnt);
}

// ---------------------------------------------------------------------------
// Kernel C: out[b,i,j] = mask[b,i,j] ? rdeg_i * rdeg_j : 0   (write-bound)
// ---------------------------------------------------------------------------
__global__ __launch_bounds__(256)
void normalize_kernel(float* __restrict__ out)
{
    const size_t idx = (size_t)blockIdx.x * blockDim.x + threadIdx.x;
    const int f   = (int)(idx & 127);
    const int row = (int)(idx >> 7);
    const int b   = row >> 9;

    const int j    = f >> 5;
    const int lane = f & 31;

    const uint4 mw = *(const uint4*)(g_mask + row * 16 + 4 * j);
    const float ri = g_rdeg[row];
    const float* rj = g_rdeg + b * NN + f * 4;

    float4 o;
    o.x = ((mw.x >> lane) & 1u) ? ri * rj[0] : 0.0f;
    o.y = ((mw.y >> lane) & 1u) ? ri * rj[1] : 0.0f;
    o.z = ((mw.z >> lane) & 1u) ? ri * rj[2] : 0.0f;
    o.w = ((mw.w >> lane) & 1u) ? ri * rj[3] : 0.0f;
    ((float4*)out)[idx] = o;
}

// ---------------------------------------------------------------------------
extern "C" void kernel_launch(void* const* d_in, const int* in_sizes, int n_in,
                              void* d_out, int out_size)
{
    const float* x = (const float*)d_in[0];
    float* out = (float*)d_out;

    cudaFuncSetAttribute(gemm_ws_kernel,
                         cudaFuncAttributeMaxDynamicSharedMemorySize, SMEM_TOTAL);

    dim3 gGemm(10, BB);
    gemm_ws_kernel<<<gGemm, NTHR, SMEM_TOTAL>>>(x);

    topk_threshold_kernel<<<BB * NN / 8, 256>>>();

    const int n4 = BB * NN * NN / 4;
    normalize_kernel<<<n4 / 256, 256>>>(out);
}